// round 17
// baseline (speedup 1.0000x reference)
#include <cuda_runtime.h>
#include <cuda_fp16.h>
#include <cstdint>

// ---------------- problem constants ----------------
#define BW     1024
#define NTOK   49
#define CDIM   384
#define NHEAD  12
#define MROWS  (BW * NTOK)   // 50176
#define OS     19267584      // 50176*384
#define ATTN_SCALE 0.17677669529663687f

// ---------------- scratch (device globals) ----------------
__device__ __half g_qkvh[57802752];               // [50176,1152] fp16 (attn input)
__device__ __half g_vs16[19267584];
__device__ __half g_vsh16[19267584];
__device__ __half g_xhi[19267584];
__device__ __half g_schi[19267584];
__device__ __half g_shhi[19267584];
__device__ __half g_ohi[57802752];                // attn out, 3 streams
__device__ __half g_whi[1179648];                 // all weights (fp16)
__device__ float  g_bias[460992];                 // fused rpb+mask: [16][12][49][49]
#define WOFF_QKV  0
#define WOFF_VS   442368
#define WOFF_VSH  589824
#define WOFF_PX   737280
#define WOFF_PS   884736
#define WOFF_PSH  1032192

// =====================================================================
// helpers
// =====================================================================
__device__ __forceinline__ uint32_t smem_u32(const void* p) {
    uint32_t a;
    asm("{ .reg .u64 t; cvta.to.shared.u64 t, %1; cvt.u32.u64 %0, t; }" : "=r"(a) : "l"(p));
    return a;
}
__device__ __forceinline__ void ldsm_x4(uint32_t* r, uint32_t addr) {
    asm volatile("ldmatrix.sync.aligned.m8n8.x4.shared.b16 {%0,%1,%2,%3}, [%4];"
        : "=r"(r[0]), "=r"(r[1]), "=r"(r[2]), "=r"(r[3]) : "r"(addr));
}
__device__ __forceinline__ void ldsm_x4t(uint32_t* r, uint32_t addr) {
    asm volatile("ldmatrix.sync.aligned.m8n8.x4.trans.shared.b16 {%0,%1,%2,%3}, [%4];"
        : "=r"(r[0]), "=r"(r[1]), "=r"(r[2]), "=r"(r[3]) : "r"(addr));
}
__device__ __forceinline__ void mma16816(float* d, const uint32_t* a, uint32_t b0, uint32_t b1) {
    asm volatile("mma.sync.aligned.m16n8k16.row.col.f32.f16.f16.f32 "
        "{%0,%1,%2,%3}, {%4,%5,%6,%7}, {%8,%9}, {%0,%1,%2,%3};"
        : "+f"(d[0]), "+f"(d[1]), "+f"(d[2]), "+f"(d[3])
        : "r"(a[0]), "r"(a[1]), "r"(a[2]), "r"(a[3]), "r"(b0), "r"(b1));
}
#define CP_ASYNC16(dst, src) asm volatile("cp.async.cg.shared.global [%0], [%1], 16;" :: "r"(dst), "l"(src))
#define CP_COMMIT()          asm volatile("cp.async.commit_group;" ::: "memory")
#define CP_WAIT(n)           asm volatile("cp.async.wait_group %0;" :: "n"(n) : "memory")

// =====================================================================
// converts
// =====================================================================
struct CvtPtrs {
    const float* src[3];
    __half* hi[3];
};
__global__ void __launch_bounds__(256) cvt_act_kernel(CvtPtrs P, int n4)
{
    int i = blockIdx.x * 256 + threadIdx.x;
    if (i >= n4) return;
    const float* src = P.src[blockIdx.z];
    float4 v = ((const float4*)src)[i];
    __half2 a = __floats2half2_rn(v.x, v.y);
    __half2 b = __floats2half2_rn(v.z, v.w);
    ((uint2*)P.hi[blockIdx.z])[i] = make_uint2(*(uint32_t*)&a, *(uint32_t*)&b);
}

// weights -> fp16 (blocks 0..1151) AND fused rpb+mask bias table (blocks 1152..1343)
__global__ void __launch_bounds__(256) cvt_w_bias_kernel(
    const float* __restrict__ w0, const float* __restrict__ w1,
    const float* __restrict__ w2, const float* __restrict__ w3,
    const float* __restrict__ w4, const float* __restrict__ w5,
    __half* __restrict__ hi,
    const float* __restrict__ mask, const float* __restrict__ rpb,
    float* __restrict__ tab)
{
    const int blk = blockIdx.x;
    if (blk >= 1152) {
        const int q = blk - 1152;
        const int m16 = q / 12;
        const int h   = q - m16 * 12;
        float* dst = tab + ((size_t)m16 * 12 + h) * 2401;
        const float* msk = mask + (size_t)m16 * 2401;
        for (int idx = threadIdx.x; idx < 2401; idx += 256) {
            int i = idx / 49, j = idx - i * 49;
            int yi = i / 7, xi = i - yi * 7;
            int yj = j / 7, xj = j - yj * 7;
            int ridx = (yi - yj + 6) * 13 + (xi - xj + 6);
            dst[idx] = rpb[ridx * 12 + h] + msk[idx];
        }
        return;
    }
    int i = blk * 256 + threadIdx.x;
    const float* src;
    int k;
    if (i < 110592) { src = w0; k = i; }
    else {
        int j = i - 110592;
        int seg = j / 36864;
        k = j - seg * 36864;
        src = (seg == 0) ? w1 : (seg == 1) ? w2 : (seg == 2) ? w3 : (seg == 3) ? w4 : w5;
    }
    float4 v = ((const float4*)src)[k];
    __half2 a = __floats2half2_rn(v.x, v.y);
    __half2 b = __floats2half2_rn(v.z, v.w);
    ((uint2*)hi)[i] = make_uint2(*(uint32_t*)&a, *(uint32_t*)&b);
}

// ---------------- GEMM smem layout: 64x128 CTA tile, K=32 stages ----------
// A tile [64][40h] pitch 80B = 5120B ; B tile [32][136h] pitch 272B = 8704B
#define GB_OFF   5120
#define GSTAGE_B 13824
#define GNSTAGE  4
#define GEMM_SMEM_BYTES (GNSTAGE * GSTAGE_B)
#define MT_PER_CTA 4
#define GNST_TOT (MT_PER_CTA * 12)   // 48 K32-stages over 4 M64 tiles

struct GemmPtrs {
    const __half* ahi[3];
    const __half* w[3];
    const float*  bias[3];
    float*        c[3];
    __half*       ch[3];
    int           n[3];
    int           nx0, nx01;
};

// =====================================================================
// fp16 GEMM: C[M,N] = A @ W + bias.  CTA 64x128, warp 16x64, 3 CTAs/SM.
// =====================================================================
__global__ void __launch_bounds__(256, 3) gemm_mma_kernel(GemmPtrs P)
{
    const int bx = blockIdx.x;
    int z, bnb;
    if (bx < P.nx0)       { z = 0; bnb = bx; }
    else if (bx < P.nx01) { z = 1; bnb = bx - P.nx0; }
    else                  { z = 2; bnb = bx - P.nx01; }
    const int N  = P.n[z];
    const int bn = bnb << 7;

    extern __shared__ char sm[];
    const uint32_t sb = smem_u32(sm);
    const __half* __restrict__ Ahi = P.ahi[z];
    const __half* __restrict__ Whi = P.w[z];
    const float*  __restrict__ bias = P.bias[z];
    float* __restrict__ C  = P.c[z];
    __half* __restrict__ CH = P.ch[z];

    const int tid  = threadIdx.x;
    const int lane = tid & 31;
    const int wid  = tid >> 5;
    const int wm   = wid >> 1;       // 0..3 (16-row strip)
    const int wn   = wid & 1;        // 0..1 (64-col half)
    const int t0   = blockIdx.y * MT_PER_CTA;

    // fragment base offsets (bytes within a stage)
    const uint32_t aoff = (uint32_t)((wm * 16 + (lane & 15)) * 80 + ((lane >> 4) << 4));
    const uint32_t boff = (uint32_t)((lane & 15) * 272 + wn * 128 + ((lane >> 4) << 4));

    float acc[8][4];
#pragma unroll
    for (int ni = 0; ni < 8; ni++)
#pragma unroll
        for (int r = 0; r < 4; r++) acc[ni][r] = 0.f;

    // staging indices
    const int ar = tid >> 2;         // 0..63
    const int ac = tid & 3;          // 0..3 (16B chunk)
    const int br0 = tid >> 4;        // 0..15
    const int bc  = tid & 15;

#define ISSUE_STAGE(s) do { \
    const int t_  = (s) / 12; \
    const int kc_ = (s) - t_ * 12; \
    const int bm_ = (t0 + t_) << 6; \
    const uint32_t std_ = sb + (uint32_t)((s) % GNSTAGE) * GSTAGE_B; \
    size_t asrc = (size_t)(bm_ + ar) * CDIM + kc_ * 32 + ac * 8; \
    CP_ASYNC16(std_ + ar * 80 + ac * 16, Ahi + asrc); \
    _Pragma("unroll") \
    for (int p = 0; p < 2; p++) { \
        int brr = br0 + p * 16; \
        size_t bsrc = (size_t)(kc_ * 32 + brr) * N + bn + bc * 8; \
        CP_ASYNC16(std_ + GB_OFF + brr * 272 + bc * 16, Whi + bsrc); \
    } \
} while (0)

    ISSUE_STAGE(0); CP_COMMIT();
    ISSUE_STAGE(1); CP_COMMIT();
    ISSUE_STAGE(2); CP_COMMIT();

    const int mrow0 = wm * 16 + (lane >> 2);
    const int ncol0 = bn + wn * 64 + ((lane & 3) << 1);

#pragma unroll 1
    for (int s = 0; s < GNST_TOT; s++) {
        if (s + 2 < GNST_TOT)      { CP_WAIT(2); }
        else if (s + 1 < GNST_TOT) { CP_WAIT(1); }
        else                       { CP_WAIT(0); }
        __syncthreads();
        if (s + 3 < GNST_TOT) { ISSUE_STAGE(s + 3); CP_COMMIT(); }

        const uint32_t st = sb + (uint32_t)(s % GNSTAGE) * GSTAGE_B;
#pragma unroll
        for (int ks = 0; ks < 2; ks++) {
            uint32_t a[4];
            ldsm_x4(a, st + aoff + ks * 32);
            const uint32_t bbase = st + GB_OFF + boff + (uint32_t)(ks * 16 * 272);
#pragma unroll
            for (int np = 0; np < 4; np++) {
                uint32_t bh[4];
                ldsm_x4t(bh, bbase + np * 32);
                mma16816(acc[np * 2],     a, bh[0], bh[1]);
                mma16816(acc[np * 2 + 1], a, bh[2], bh[3]);
            }
        }

        if ((s % 12) == 11) {
            const int bm_ = (t0 + s / 12) << 6;
#pragma unroll
            for (int ni = 0; ni < 8; ni++) {
                const int n = ncol0 + ni * 8;
                const float2 b2 = *(const float2*)(bias + n);
                const int m = bm_ + mrow0;
                if (CH) {
                    __half2 h0 = __floats2half2_rn(acc[ni][0] + b2.x, acc[ni][1] + b2.y);
                    __half2 h1 = __floats2half2_rn(acc[ni][2] + b2.x, acc[ni][3] + b2.y);
                    *(uint32_t*)&CH[(size_t)m * N + n]       = *(uint32_t*)&h0;
                    *(uint32_t*)&CH[(size_t)(m + 8) * N + n] = *(uint32_t*)&h1;
                } else {
                    *(float2*)(C + (size_t)m * N + n) =
                        make_float2(acc[ni][0] + b2.x, acc[ni][1] + b2.y);
                    *(float2*)(C + (size_t)(m + 8) * N + n) =
                        make_float2(acc[ni][2] + b2.x, acc[ni][3] + b2.y);
                }
                acc[ni][0] = 0.f; acc[ni][1] = 0.f;
                acc[ni][2] = 0.f; acc[ni][3] = 0.f;
            }
        }
    }
}

// =====================================================================
// Attention v7: 4 heads per block, cp.async prefetch pipeline. (unchanged)
// =====================================================================
#define AQKB  10240
#define AVV   20480
#define ASC   35840
#define ATTN_NH 4

__global__ __launch_bounds__(256) void attn_kernel(const float* __restrict__ biasTab)
{
    __shared__ __align__(16) char blob[46032];

    const int w  = blockIdx.x;
    const int h0 = blockIdx.y * ATTN_NH;

    const int tid  = threadIdx.x;
    const int lane = tid & 31;
    const int wid  = tid >> 5;
    const uint32_t sb = smem_u32(blob);
    float* sattn = (float*)(blob + ASC);

    {
        uint4 z4 = make_uint4(0, 0, 0, 0);
        for (int i = tid; i < 225; i += 256) {
            int arr = i / 75;
            int o   = i - arr * 75;
            char* base = blob + AVV + arr * 5120;
            ((uint4*)(base + 49 * 80))[o] = z4;
        }
    }

#define STAGE_QK(hh, bb) do { \
    if (tid < 196) { \
        int n_ = tid >> 2, c8_ = (tid & 3) << 3; \
        const __half* qrow_ = g_qkvh + ((size_t)w * 49 + n_) * 1152 + (hh) * 32 + c8_; \
        uint32_t dst_ = sb + (uint32_t)(bb) * AQKB + (uint32_t)(n_ * 40 + c8_) * 2; \
        CP_ASYNC16(dst_, qrow_); \
        CP_ASYNC16(dst_ + 5120, qrow_ + 384); \
    } \
    CP_COMMIT(); \
} while (0)

#define STAGE_VST(hh) do { \
    if (tid < 196) { \
        int n_ = tid >> 2, c8_ = (tid & 3) << 3; \
        const __half* vrow_ = g_qkvh + ((size_t)w * 49 + n_) * 1152 + (hh) * 32 + 768 + c8_; \
        size_t voff_ = ((size_t)w * 49 + n_) * 384 + (hh) * 32 + c8_; \
        uint32_t dst_ = sb + AVV + (uint32_t)(n_ * 40 + c8_) * 2; \
        CP_ASYNC16(dst_, vrow_); \
        CP_ASYNC16(dst_ + 5120, g_vs16 + voff_); \
        CP_ASYNC16(dst_ + 10240, g_vsh16 + voff_); \
    } \
    CP_COMMIT(); \
} while (0)

    STAGE_QK(h0, 0);
    STAGE_VST(h0);

#pragma unroll 1
    for (int it = 0; it < ATTN_NH; it++) {
        const int h = h0 + it;
        const int b = it & 1;
        if (it + 1 < ATTN_NH) { STAGE_QK(h + 1, 1 - b); }
        if (it == 0) { CP_WAIT(1); }
        __syncthreads();

        const uint32_t uQ = sb + (uint32_t)b * AQKB;
        const uint32_t uK = uQ + 5120;
        __half* sP = (__half*)(blob + b * AQKB);

        {
            const int wm = wid & 3;
            const int wn = wid >> 2;
            float d[4][4];
#pragma unroll
            for (int nt = 0; nt < 4; nt++)
#pragma unroll
                for (int r = 0; r < 4; r++) d[nt][r] = 0.f;

            const uint32_t abase = uQ + (uint32_t)(((wm * 16 + (lane & 15)) * 40 + ((lane >> 4) << 3)) << 1);
#pragma unroll
            for (int ks = 0; ks < 2; ks++) {
                uint32_t a[4];
                ldsm_x4(a, abase + ks * 32);
#pragma unroll
                for (int g = 0; g < 2; g++) {
                    uint32_t bb[4];
                    const uint32_t bbase = uK + (uint32_t)(((wn * 32 + g * 16 + (lane & 15)) * 40 + ((lane >> 4) << 3)) << 1);
                    ldsm_x4(bb, bbase + ks * 32);
                    mma16816(d[g * 2 + 0], a, bb[0], bb[2]);
                    mma16816(d[g * 2 + 1], a, bb[1], bb[3]);
                }
            }
            const int row0 = wm * 16 + (lane >> 2);
            const int row1 = row0 + 8;
#pragma unroll
            for (int nt = 0; nt < 4; nt++) {
                const int col = wn * 32 + nt * 8 + ((lane & 3) << 1);
                if (col < 49) {
                    if (row0 < 49) {
                        sattn[row0 * 52 + col] = d[nt][0];
                        if (col < 48) sattn[row0 * 52 + col + 1] = d[nt][1];
                    }
                    if (row1 < 49) {
                        sattn[row1 * 52 + col] = d[nt][2];
                        if (col < 48) sattn[row1 * 52 + col + 1] = d[nt][3];
                    }
                }
            }
        }
        __syncthreads();

        {
            uint4 z4 = make_uint4(0, 0, 0, 0);
            for (int i = tid; i < 128; i += 256) {
                int r = i >> 1;
                int o = i & 1;
                ((uint4*)(sP + r * 72 + 48))[o] = z4;
            }
        }
        {
            const float* brow = biasTab + ((size_t)(w & 15) * 12 + h) * 2401;
            const int j1 = lane;
            const int j2 = lane + 32;
            for (int r = wid; r < 49; r += 8) {
                float x1 = -1e30f, x2 = -1e30f;
                if (j1 < 49) x1 = sattn[r * 52 + j1] * ATTN_SCALE + brow[r * 49 + j1];
                if (j2 < 49) x2 = sattn[r * 52 + j2] * ATTN_SCALE + brow[r * 49 + j2];
                float m = fmaxf(x1, x2);
#pragma unroll
                for (int o = 16; o > 0; o >>= 1)
                    m = fmaxf(m, __shfl_xor_sync(0xffffffffu, m, o));
                float e1 = (j1 < 49) ? __expf(x1 - m) : 0.f;
                float e2 = (j2 < 49) ? __expf(x2 - m) : 0.f;
                float s = e1 + e2;
#pragma unroll
                for (int o = 16; o > 0; o >>= 1)
                    s += __shfl_xor_sync(0xffffffffu, s, o);
                float inv = 1.f / s;
                if (j1 < 49) sP[r * 72 + j1] = __float2half_rn(e1 * inv);
                if (j2 < 49) sP[r * 72 + j2] = __float2half_rn(e2 * inv);
            }
        }
        CP_WAIT(0);
        __syncthreads();

        {
            const uint32_t uP = sb + (uint32_t)b * AQKB;
            const size_t obase = (size_t)w * 49 * 384 + h * 32;
#pragma unroll
            for (int rep = 0; rep < 3; rep++) {
                const int u = wid + rep * 8;
                const int s  = u >> 3;
                const int mz = (u >> 1) & 3;
                const int nh = u & 1;
                const uint32_t uV = sb + AVV + (uint32_t)s * 5120;

                float d[2][4];
#pragma unroll
                for (int nt = 0; nt < 2; nt++)
#pragma unroll
                    for (int r = 0; r < 4; r++) d[nt][r] = 0.f;

                const uint32_t abase = uP + (uint32_t)(((mz * 16 + (lane & 15)) * 72 + ((lane >> 4) << 3)) << 1);
                const uint32_t bbase = uV + (uint32_t)((((lane & 15)) * 40 + ((lane >> 4) << 3) + nh * 16) << 1);
#pragma unroll
                for (int ks = 0; ks < 4; ks++) {
                    uint32_t a[4], bb[4];
                    ldsm_x4(a, abase + ks * 32);
                    ldsm_x4t(bb, bbase + (uint32_t)(ks * 16 * 80));
                    mma16816(d[0], a, bb[0], bb[1]);
                    mma16816(d[1], a, bb[2], bb[3]);
                }
                const int row0 = mz * 16 + (lane >> 2);
                const int row1 = row0 + 8;
#pragma unroll
                for (int nt = 0; nt < 2; nt++) {
                    const int dc = nh * 16 + nt * 8 + ((lane & 3) << 1);
                    if (row0 < 49) {
                        __half2 p = __floats2half2_rn(d[nt][0], d[nt][1]);
                        *(uint32_t*)&g_ohi[(size_t)s * OS + obase + (size_t)row0 * 384 + dc] = *(uint32_t*)&p;
                    }
                    if (row1 < 49) {
                        __half2 p = __floats2half2_rn(d[nt][2], d[nt][3]);
                        *(uint32_t*)&g_ohi[(size_t)s * OS + obase + (size_t)row1 * 384 + dc] = *(uint32_t*)&p;
                    }
                }
            }
        }
        __syncthreads();
        if (it + 1 < ATTN_NH) { STAGE_VST(h + 1); }
    }
}

// =====================================================================
// launch
// =====================================================================
extern "C" void kernel_launch(void* const* d_in, const int* in_sizes, int n_in,
                              void* d_out, int out_size)
{
    (void)in_sizes; (void)n_in; (void)out_size;

    const float* x            = (const float*)d_in[0];
    const float* scale        = (const float*)d_in[1];
    const float* shift        = (const float*)d_in[2];
    const float* mask         = (const float*)d_in[3];
    const float* qkv_w        = (const float*)d_in[4];
    const float* qkv_b        = (const float*)d_in[5];
    const float* vscale_w     = (const float*)d_in[6];
    const float* vscale_b     = (const float*)d_in[7];
    const float* vshift_w     = (const float*)d_in[8];
    const float* vshift_b     = (const float*)d_in[9];
    const float* rpb_table    = (const float*)d_in[10];
    const float* proj_x_w     = (const float*)d_in[11];
    const float* proj_x_b     = (const float*)d_in[12];
    const float* proj_scale_w = (const float*)d_in[13];
    const float* proj_scale_b = (const float*)d_in[14];
    const float* proj_shift_w = (const float*)d_in[15];
    const float* proj_shift_b = (const float*)d_in[16];
    float* out = (float*)d_out;

    __half *p_qkvh, *p_vs16, *p_vsh16;
    __half *p_xhi, *p_schi, *p_shhi;
    __half *p_ohi, *p_whi;
    float  *p_bias;
    cudaGetSymbolAddress((void**)&p_qkvh,  g_qkvh);
    cudaGetSymbolAddress((void**)&p_vs16,  g_vs16);
    cudaGetSymbolAddress((void**)&p_vsh16, g_vsh16);
    cudaGetSymbolAddress((void**)&p_xhi,  g_xhi);
    cudaGetSymbolAddress((void**)&p_schi, g_schi);
    cudaGetSymbolAddress((void**)&p_shhi, g_shhi);
    cudaGetSymbolAddress((void**)&p_ohi,  g_ohi);
    cudaGetSymbolAddress((void**)&p_whi,  g_whi);
    cudaGetSymbolAddress((void**)&p_bias, g_bias);

    cudaFuncSetAttribute(gemm_mma_kernel,
                         cudaFuncAttributeMaxDynamicSharedMemorySize, GEMM_SMEM_BYTES);

    dim3 blk(256);
    const int gy = MROWS / 64 / MT_PER_CTA;   // 196
    const int nact4 = OS / 4;

    // launch 1: weights + bias table (merged)
    cvt_w_bias_kernel<<<1344, 256>>>(qkv_w, vscale_w, vshift_w, proj_x_w, proj_scale_w,
                                     proj_shift_w, p_whi, mask, rpb_table, p_bias);

    // launch 2: activation conversions
    {
        CvtPtrs C = {};
        C.src[0] = x;     C.hi[0] = p_xhi;
        C.src[1] = scale; C.hi[1] = p_schi;
        C.src[2] = shift; C.hi[2] = p_shhi;
        cvt_act_kernel<<<dim3((nact4 + 255) / 256, 1, 3), blk>>>(C, nact4);
    }

    // launch 3: input GEMMs (flat map, fp16 out)
    {
        GemmPtrs P = {};
        P.ahi[0] = p_xhi;  P.w[0] = p_whi + WOFF_QKV;
        P.bias[0] = qkv_b;    P.ch[0] = p_qkvh;  P.n[0] = 1152;
        P.ahi[1] = p_schi; P.w[1] = p_whi + WOFF_VS;
        P.bias[1] = vscale_b; P.ch[1] = p_vs16;  P.n[1] = 384;
        P.ahi[2] = p_shhi; P.w[2] = p_whi + WOFF_VSH;
        P.bias[2] = vshift_b; P.ch[2] = p_vsh16; P.n[2] = 384;
        P.nx0 = 9; P.nx01 = 12;
        gemm_mma_kernel<<<dim3(15, gy, 1), blk, GEMM_SMEM_BYTES>>>(P);
    }

    // launch 4: attention (profiled slot)
    attn_kernel<<<dim3(BW, NHEAD / ATTN_NH), blk>>>(p_bias);

    // launch 5: 3 output projections (flat map, fp32 out)
    {
        GemmPtrs P = {};
        P.ahi[0] = p_ohi;          P.w[0] = p_whi + WOFF_PX;
        P.bias[0] = proj_x_b;      P.c[0] = out;          P.n[0] = 384;
        P.ahi[1] = p_ohi + OS;     P.w[1] = p_whi + WOFF_PS;
        P.bias[1] = proj_scale_b;  P.c[1] = out + OS;     P.n[1] = 384;
        P.ahi[2] = p_ohi + 2 * OS; P.w[2] = p_whi + WOFF_PSH;
        P.bias[2] = proj_shift_b;  P.c[2] = out + 2 * OS; P.n[2] = 384;
        P.nx0 = 3; P.nx01 = 6;
        gemm_mma_kernel<<<dim3(9, gy, 1), blk, GEMM_SMEM_BYTES>>>(P);
    }
}